// round 1
// baseline (speedup 1.0000x reference)
#include <cuda_runtime.h>
#include <cuda_bf16.h>
#include <math.h>

#define T_STEPS 4096
#define FD 32
#define SD 16
#define HD 48
#define VOCAB 50257

#define VBLOCK 2048
#define NVB ((VOCAB + VBLOCK - 1) / VBLOCK)   // 25
#define TT 32
#define NTB (T_STEPS / TT)                     // 128

// ---------------- scratch (no dynamic allocation allowed) ----------------
__device__ float g_xg[T_STEPS * FD];   // W_gate_x @ x_t
__device__ float g_xp[T_STEPS * FD];   // W_x_proj @ x_t
__device__ float g_xd[T_STEPS * FD];   // W_x_fast @ x_t
__device__ float g_h [T_STEPS * HD];   // concat(h_fast, h_slow) per step
__device__ float g_partial[NVB * T_STEPS];
__device__ float g_nll[T_STEPS];

__device__ __forceinline__ float sigmoid_f(float x) {
    return 1.0f / (1.0f + __expf(-x));
}

// ============================================================
// K1: precompute token-dependent drives (fully parallel)
// ============================================================
__global__ void precompute_kernel(const int* __restrict__ tok,
                                  const float* __restrict__ embed,
                                  const float* __restrict__ Wgx,
                                  const float* __restrict__ Wxp,
                                  const float* __restrict__ Wxf)
{
    int t = blockIdx.x;
    int i = threadIdx.x;          // 0..31
    __shared__ __align__(16) float xs[FD];
    int tk = tok[t];
    xs[i] = embed[(size_t)tk * FD + i];
    __syncwarp();
    float a = 0.f, b = 0.f, c = 0.f;
#pragma unroll
    for (int j = 0; j < FD; j++) {
        float x = xs[j];
        a = fmaf(Wgx[i * FD + j], x, a);
        b = fmaf(Wxp[i * FD + j], x, b);
        c = fmaf(Wxf[i * FD + j], x, c);
    }
    g_xg[t * FD + i] = a;
    g_xp[t * FD + i] = b;
    g_xd[t * FD + i] = c;
}

// ============================================================
// K2: the sequential scan. One warp; thread i owns state lane i.
// Weights live in registers; state broadcast through shared memory.
// ============================================================
__global__ void __launch_bounds__(32, 1) scan_kernel(
    const float* __restrict__ Wgh, const float* __restrict__ bgh_p,
    const float* __restrict__ Wff, const float* __restrict__ bff_p,
    const float* __restrict__ Wfs,
    const float* __restrict__ Wsgf, const float* __restrict__ bsgf,
    const float* __restrict__ Wsgs,
    const float* __restrict__ Wss, const float* __restrict__ bss,
    const float* __restrict__ Wsf)
{
    int i = threadIdx.x;
    __shared__ __align__(16) float shf[FD];   // h_fast
    __shared__ __align__(16) float shs[SD];   // h_slow
    __shared__ __align__(16) float stmp[FD];  // exchange buffer
    const float4* shf4 = reinterpret_cast<const float4*>(shf);
    const float4* shs4 = reinterpret_cast<const float4*>(shs);

    // per-thread register-resident weight rows
    float wgh[FD], wff[FD], wfs[SD], ws[FD + SD];
#pragma unroll
    for (int j = 0; j < FD; j++) { wgh[j] = Wgh[i * FD + j]; wff[j] = Wff[i * FD + j]; }
#pragma unroll
    for (int j = 0; j < SD; j++) wfs[j] = Wfs[i * SD + j];
    if (i < SD) {
#pragma unroll
        for (int j = 0; j < FD; j++) ws[j] = Wsgf[i * FD + j];
#pragma unroll
        for (int j = 0; j < SD; j++) ws[FD + j] = Wsgs[i * SD + j];
    } else {
        int ii = i - SD;
#pragma unroll
        for (int j = 0; j < FD; j++) ws[j] = Wsf[ii * FD + j];
#pragma unroll
        for (int j = 0; j < SD; j++) ws[FD + j] = Wss[ii * SD + j];
    }
    float bgh = bgh_p[i];
    float bff = bff_p[i];
    float bs  = (i < SD) ? bsgf[i] : bss[i - SD];

    shf[i] = 0.f;
    if (i < SD) shs[i] = 0.f;
    __syncwarp();

    // prefetch drives for t=0
    float xg = g_xg[i], xp = g_xp[i], xd = g_xd[i];

    for (int t = 0; t < T_STEPS; t++) {
        // prefetch next step's drives (hidden behind this step's work)
        float nxg = 0.f, nxp = 0.f, nxd = 0.f;
        if (t + 1 < T_STEPS) {
            nxg = g_xg[(t + 1) * FD + i];
            nxp = g_xp[(t + 1) * FD + i];
            nxd = g_xd[(t + 1) * FD + i];
        }

        // s_drive = W_fs @ h_slow   (h_slow from previous step, fixed in relax)
        float sdrive;
        {
            float a0 = 0.f, a1 = 0.f, a2 = 0.f, a3 = 0.f;
#pragma unroll
            for (int q = 0; q < SD / 4; q++) {
                float4 h4 = shs4[q];
                a0 = fmaf(wfs[q * 4 + 0], h4.x, a0);
                a1 = fmaf(wfs[q * 4 + 1], h4.y, a1);
                a2 = fmaf(wfs[q * 4 + 2], h4.z, a2);
                a3 = fmaf(wfs[q * 4 + 3], h4.w, a3);
            }
            sdrive = (a0 + a1) + (a2 + a3);
        }

        // gate = sigmoid(W_gate_h @ h_fast + b + xg)
        float acc;
        {
            float a0 = 0.f, a1 = 0.f, a2 = 0.f, a3 = 0.f;
#pragma unroll
            for (int q = 0; q < FD / 4; q++) {
                float4 h4 = shf4[q];
                a0 = fmaf(wgh[q * 4 + 0], h4.x, a0);
                a1 = fmaf(wgh[q * 4 + 1], h4.y, a1);
                a2 = fmaf(wgh[q * 4 + 2], h4.z, a2);
                a3 = fmaf(wgh[q * 4 + 3], h4.w, a3);
            }
            acc = (a0 + a1) + (a2 + a3);
        }
        float hf = shf[i];
        __syncwarp();                       // all reads of shf done
        float gate = sigmoid_f(acc + bgh + xg);
        hf = hf + gate * xp;
        shf[i] = hf;
        __syncwarp();

        // two relaxation iterations: target = tanh(W_ff@h + bff + sdrive + xd)
#pragma unroll
        for (int r = 0; r < 2; r++) {
            float a0 = bff + sdrive + xd, a1 = 0.f, a2 = 0.f, a3 = 0.f;
#pragma unroll
            for (int q = 0; q < FD / 4; q++) {
                float4 h4 = shf4[q];
                a0 = fmaf(wff[q * 4 + 0], h4.x, a0);
                a1 = fmaf(wff[q * 4 + 1], h4.y, a1);
                a2 = fmaf(wff[q * 4 + 2], h4.z, a2);
                a3 = fmaf(wff[q * 4 + 3], h4.w, a3);
            }
            __syncwarp();                   // reads done before write
            float tgt = tanhf((a0 + a1) + (a2 + a3));
            hf = hf + 0.25f * (tgt - hf);
            shf[i] = hf;
            __syncwarp();
        }

        // slow path: lanes 0..15 -> slow_gate, lanes 16..31 -> slow_target
        float sacc = bs;
        {
            float a0 = 0.f, a1 = 0.f, a2 = 0.f, a3 = 0.f;
#pragma unroll
            for (int q = 0; q < FD / 4; q++) {
                float4 h4 = shf4[q];
                a0 = fmaf(ws[q * 4 + 0], h4.x, a0);
                a1 = fmaf(ws[q * 4 + 1], h4.y, a1);
                a2 = fmaf(ws[q * 4 + 2], h4.z, a2);
                a3 = fmaf(ws[q * 4 + 3], h4.w, a3);
            }
#pragma unroll
            for (int q = 0; q < SD / 4; q++) {
                float4 h4 = shs4[q];
                a0 = fmaf(ws[FD + q * 4 + 0], h4.x, a0);
                a1 = fmaf(ws[FD + q * 4 + 1], h4.y, a1);
                a2 = fmaf(ws[FD + q * 4 + 2], h4.z, a2);
                a3 = fmaf(ws[FD + q * 4 + 3], h4.w, a3);
            }
            sacc += (a0 + a1) + (a2 + a3);
        }
        float val = (i < SD) ? sigmoid_f(sacc) : tanhf(sacc);
        stmp[i] = val;
        float hs_old = (i < SD) ? shs[i] : 0.f;
        __syncwarp();                       // stmp visible; shs reads done
        float hs_new = 0.f;
        if (i < SD)
            hs_new = hs_old + 0.02f * val * (stmp[SD + i] - hs_old);

        // emit state, update h_slow
        g_h[t * HD + i] = hf;
        if (i < SD) {
            shs[i] = hs_new;
            g_h[t * HD + FD + i] = hs_new;
        }
        xg = nxg; xp = nxp; xd = nxd;
        __syncwarp();
    }
}

// ============================================================
// K3: output head — partial sumexp over a vocab block for 32 timesteps.
// grid (NVB, NTB), 256 threads. No max needed: |logit| <= ~0.4.
// ============================================================
__global__ void __launch_bounds__(256) head_kernel(const float* __restrict__ Wout,
                                                   const float* __restrict__ bout)
{
    int vb = blockIdx.x;
    int tb = blockIdx.y;
    int tid = threadIdx.x;

    __shared__ __align__(16) float hsh[TT][HD];
    const float* hsrc = g_h + (size_t)tb * TT * HD;
    for (int k = tid; k < TT * HD; k += 256)
        ((float*)hsh)[k] = hsrc[k];
    __syncthreads();

    float acc[TT];
#pragma unroll
    for (int q = 0; q < TT; q++) acc[q] = 0.f;

    for (int vi = 0; vi < VBLOCK / 256; vi++) {
        int v = vb * VBLOCK + vi * 256 + tid;
        if (v < VOCAB) {
            float w[HD];
            const float4* wp = (const float4*)(Wout + (size_t)v * HD);
#pragma unroll
            for (int q = 0; q < HD / 4; q++) {
                float4 f = wp[q];
                w[q * 4 + 0] = f.x; w[q * 4 + 1] = f.y;
                w[q * 4 + 2] = f.z; w[q * 4 + 3] = f.w;
            }
            float bo = bout[v];
#pragma unroll 4
            for (int tt = 0; tt < TT; tt++) {
                float a0 = bo, a1 = 0.f, a2 = 0.f, a3 = 0.f;
#pragma unroll
                for (int k = 0; k < HD; k += 4) {
                    a0 = fmaf(w[k + 0], hsh[tt][k + 0], a0);
                    a1 = fmaf(w[k + 1], hsh[tt][k + 1], a1);
                    a2 = fmaf(w[k + 2], hsh[tt][k + 2], a2);
                    a3 = fmaf(w[k + 3], hsh[tt][k + 3], a3);
                }
                acc[tt] += __expf((a0 + a1) + (a2 + a3));
            }
        }
    }

    // block reduction: warp shuffles then cross-warp shared combine
    __shared__ float swarp[8][TT];
    int lane = tid & 31, wrp = tid >> 5;
#pragma unroll
    for (int tt = 0; tt < TT; tt++) {
        float v = acc[tt];
        v += __shfl_xor_sync(0xffffffff, v, 16);
        v += __shfl_xor_sync(0xffffffff, v, 8);
        v += __shfl_xor_sync(0xffffffff, v, 4);
        v += __shfl_xor_sync(0xffffffff, v, 2);
        v += __shfl_xor_sync(0xffffffff, v, 1);
        if (lane == 0) swarp[wrp][tt] = v;
    }
    __syncthreads();
    if (tid < TT) {
        float s = 0.f;
#pragma unroll
        for (int q = 0; q < 8; q++) s += swarp[q][tid];
        g_partial[(size_t)vb * T_STEPS + tb * TT + tid] = s;
    }
}

// ============================================================
// K4: per-timestep NLL = log(sumexp) - target_logit
// ============================================================
__global__ void nll_kernel(const int* __restrict__ tok,
                           const float* __restrict__ Wout,
                           const float* __restrict__ bout)
{
    int t = blockIdx.x * blockDim.x + threadIdx.x;
    if (t >= T_STEPS) return;
    float s = 0.f;
#pragma unroll
    for (int vb = 0; vb < NVB; vb++) s += g_partial[(size_t)vb * T_STEPS + t];
    int tgt = tok[t + 1];
    const float* wrow = Wout + (size_t)tgt * HD;
    const float* hr = g_h + t * HD;
    float a = bout[tgt];
#pragma unroll
    for (int k = 0; k < HD; k++) a = fmaf(wrow[k], hr[k], a);
    g_nll[t] = logf(s) - a;
}

// ============================================================
// K5: deterministic mean reduction
// ============================================================
__global__ void reduce_kernel(float* __restrict__ out)
{
    __shared__ float sh[256];
    int tid = threadIdx.x;
    float s = 0.f;
    for (int t = tid; t < T_STEPS; t += 256) s += g_nll[t];
    sh[tid] = s;
    __syncthreads();
    for (int st = 128; st > 0; st >>= 1) {
        if (tid < st) sh[tid] += sh[tid + st];
        __syncthreads();
    }
    if (tid == 0) out[0] = sh[0] / (float)T_STEPS;
}

// ============================================================
extern "C" void kernel_launch(void* const* d_in, const int* in_sizes, int n_in,
                              void* d_out, int out_size)
{
    const int*   tok   = (const int*)  d_in[0];   // token_ids [4097]
    const float* embed = (const float*)d_in[1];   // [VOCAB, 32]
    const float* Wgh   = (const float*)d_in[2];   // W_gate_h [32,32]
    const float* bgh   = (const float*)d_in[3];
    const float* Wgx   = (const float*)d_in[4];   // W_gate_x
    const float* Wxp   = (const float*)d_in[5];   // W_x_proj
    const float* Wff   = (const float*)d_in[6];
    const float* bff   = (const float*)d_in[7];
    const float* Wfs   = (const float*)d_in[8];   // [32,16]
    const float* Wxf   = (const float*)d_in[9];   // W_x_fast
    const float* Wsgf  = (const float*)d_in[10];  // [16,32]
    const float* bsgf  = (const float*)d_in[11];
    const float* Wsgs  = (const float*)d_in[12];  // [16,16]
    const float* Wss   = (const float*)d_in[13];  // [16,16]
    const float* bss   = (const float*)d_in[14];
    const float* Wsf   = (const float*)d_in[15];  // [16,32]
    const float* Wout  = (const float*)d_in[16];  // [VOCAB,48]
    const float* bout  = (const float*)d_in[17];

    precompute_kernel<<<T_STEPS, 32>>>(tok, embed, Wgx, Wxp, Wxf);
    scan_kernel<<<1, 32>>>(Wgh, bgh, Wff, bff, Wfs, Wsgf, bsgf, Wsgs, Wss, bss, Wsf);
    dim3 g3(NVB, NTB);
    head_kernel<<<g3, 256>>>(Wout, bout);
    nll_kernel<<<32, 128>>>(tok, Wout, bout);
    reduce_kernel<<<1, 256>>>((float*)d_out);
}

// round 2
// speedup vs baseline: 1.1565x; 1.1565x over previous
#include <cuda_runtime.h>
#include <cuda_bf16.h>
#include <math.h>

#define T_STEPS 4096
#define FD 32
#define SD 16
#define HD 48
#define VOCAB 50257

#define VBLOCK 2048
#define NVB ((VOCAB + VBLOCK - 1) / VBLOCK)   // 25
#define TT 32
#define NTB (T_STEPS / TT)                     // 128

typedef unsigned long long ull;

// ---------------- scratch (no dynamic allocation allowed) ----------------
__device__ float g_xg[T_STEPS * FD];   // W_gate_x @ x_t
__device__ float g_xp[T_STEPS * FD];   // W_x_proj @ x_t
__device__ float g_xd[T_STEPS * FD];   // W_x_fast @ x_t
__device__ float g_h [T_STEPS * HD];   // concat(h_fast, h_slow) per step
__device__ float g_partial[NVB * T_STEPS];
__device__ float g_nll[T_STEPS];

// ---------------- f32x2 packed helpers (FFMA2 — only reachable via PTX) ----
#define FMA2(acc, a, b) asm("fma.rn.f32x2 %0, %1, %2, %0;" : "+l"(acc) : "l"(a), "l"(b))
#define ADD2(d, a, b)   asm("add.rn.f32x2 %0, %1, %2;"     : "=l"(d)   : "l"(a), "l"(b))

__device__ __forceinline__ ull pack2(float lo, float hi) {
    ull r; asm("mov.b64 %0, {%1, %2};" : "=l"(r) : "f"(lo), "f"(hi)); return r;
}
__device__ __forceinline__ float redu4(ull a0, ull a1, ull a2, ull a3) {
    ull s0, s1;
    ADD2(s0, a0, a1); ADD2(s1, a2, a3); ADD2(s0, s0, s1);
    float lo, hi; asm("mov.b64 {%0, %1}, %2;" : "=f"(lo), "=f"(hi) : "l"(s0));
    return lo + hi;
}
__device__ __forceinline__ float tanh_f(float x) {
    float r; asm("tanh.approx.f32 %0, %1;" : "=f"(r) : "f"(x)); return r;
}
__device__ __forceinline__ float sig_f(float x) {      // sigmoid via HW tanh
    return fmaf(0.5f, tanh_f(0.5f * x), 0.5f);
}

// dot of 16 packed weight pairs against 8 ulonglong2 (32 floats) of shared h
__device__ __forceinline__ float dot32(const ull* w2, const ulonglong2* h2) {
    ull a0 = 0, a1 = 0, a2 = 0, a3 = 0;
#pragma unroll
    for (int m = 0; m < 8; m++) {
        ulonglong2 pp = h2[m];
        if (m & 1) { FMA2(a2, w2[2 * m], pp.x); FMA2(a3, w2[2 * m + 1], pp.y); }
        else       { FMA2(a0, w2[2 * m], pp.x); FMA2(a1, w2[2 * m + 1], pp.y); }
    }
    return redu4(a0, a1, a2, a3);
}
__device__ __forceinline__ float dot16(const ull* w2, const ulonglong2* h2) {
    ull a0 = 0, a1 = 0, a2 = 0, a3 = 0;
#pragma unroll
    for (int m = 0; m < 4; m++) {
        ulonglong2 pp = h2[m];
        if (m & 1) { FMA2(a2, w2[2 * m], pp.x); FMA2(a3, w2[2 * m + 1], pp.y); }
        else       { FMA2(a0, w2[2 * m], pp.x); FMA2(a1, w2[2 * m + 1], pp.y); }
    }
    return redu4(a0, a1, a2, a3);
}
// 48-long dot: 32 from h_fast + 16 from h_slow
__device__ __forceinline__ float dot48(const ull* w2, const ulonglong2* hf2,
                                       const ulonglong2* hs2) {
    ull a0 = 0, a1 = 0, a2 = 0, a3 = 0;
#pragma unroll
    for (int m = 0; m < 8; m++) {
        ulonglong2 pp = hf2[m];
        if (m & 1) { FMA2(a2, w2[2 * m], pp.x); FMA2(a3, w2[2 * m + 1], pp.y); }
        else       { FMA2(a0, w2[2 * m], pp.x); FMA2(a1, w2[2 * m + 1], pp.y); }
    }
#pragma unroll
    for (int m = 0; m < 4; m++) {
        ulonglong2 pp = hs2[m];
        if (m & 1) { FMA2(a2, w2[16 + 2 * m], pp.x); FMA2(a3, w2[16 + 2 * m + 1], pp.y); }
        else       { FMA2(a0, w2[16 + 2 * m], pp.x); FMA2(a1, w2[16 + 2 * m + 1], pp.y); }
    }
    return redu4(a0, a1, a2, a3);
}

// ============================================================
// K1: precompute token-dependent drives (fully parallel)
// ============================================================
__global__ void precompute_kernel(const int* __restrict__ tok,
                                  const float* __restrict__ embed,
                                  const float* __restrict__ Wgx,
                                  const float* __restrict__ Wxp,
                                  const float* __restrict__ Wxf)
{
    int t = blockIdx.x;
    int i = threadIdx.x;          // 0..31
    __shared__ __align__(16) float xs[FD];
    int tk = tok[t];
    xs[i] = embed[(size_t)tk * FD + i];
    __syncwarp();
    const ulonglong2* x2 = (const ulonglong2*)xs;
    const ull* pg = (const ull*)(Wgx + (size_t)i * FD);
    const ull* pp = (const ull*)(Wxp + (size_t)i * FD);
    const ull* pf = (const ull*)(Wxf + (size_t)i * FD);
    ull wg[16], wp[16], wf[16];
#pragma unroll
    for (int q = 0; q < 16; q++) { wg[q] = pg[q]; wp[q] = pp[q]; wf[q] = pf[q]; }
    g_xg[t * FD + i] = dot32(wg, x2);
    g_xp[t * FD + i] = dot32(wp, x2);
    g_xd[t * FD + i] = dot32(wf, x2);
}

// ============================================================
// K2: sequential scan — one warp, f32x2 packed, double-buffered h_fast,
// slow-path update of step t-1 deferred into step t (overlaps gate matvec).
// ============================================================
__global__ void __launch_bounds__(32, 1) scan_kernel(
    const float* __restrict__ Wgh, const float* __restrict__ bgh_p,
    const float* __restrict__ Wff, const float* __restrict__ bff_p,
    const float* __restrict__ Wfs,
    const float* __restrict__ Wsgf, const float* __restrict__ bsgf,
    const float* __restrict__ Wsgs,
    const float* __restrict__ Wss, const float* __restrict__ bss,
    const float* __restrict__ Wsf)
{
    int i = threadIdx.x;
    __shared__ __align__(16) float shfbuf[2 * FD];  // ping-pong h_fast
    __shared__ __align__(16) float shs[SD];         // h_slow
    __shared__ __align__(16) float stmp[FD];        // slow-path exchange

    // packed register weights (pairs along the contracted dim)
    ull wgh2[16], wff2[16], wfs2[8], ws2[24];
    {
        const ull* p0 = (const ull*)(Wgh + (size_t)i * FD);
        const ull* p1 = (const ull*)(Wff + (size_t)i * FD);
#pragma unroll
        for (int q = 0; q < 16; q++) { wgh2[q] = p0[q]; wff2[q] = p1[q]; }
        const ull* p2 = (const ull*)(Wfs + (size_t)i * SD);
#pragma unroll
        for (int q = 0; q < 8; q++) wfs2[q] = p2[q];
        if (i < SD) {
            const ull* pa = (const ull*)(Wsgf + (size_t)i * FD);
            const ull* pb = (const ull*)(Wsgs + (size_t)i * SD);
#pragma unroll
            for (int q = 0; q < 16; q++) ws2[q] = pa[q];
#pragma unroll
            for (int q = 0; q < 8; q++) ws2[16 + q] = pb[q];
        } else {
            const ull* pa = (const ull*)(Wsf + (size_t)(i - SD) * FD);
            const ull* pb = (const ull*)(Wss + (size_t)(i - SD) * SD);
#pragma unroll
            for (int q = 0; q < 16; q++) ws2[q] = pa[q];
#pragma unroll
            for (int q = 0; q < 8; q++) ws2[16 + q] = pb[q];
        }
    }
    float bgh = bgh_p[i];
    float bff = bff_p[i];
    float bs  = (i < SD) ? bsgf[i] : bss[i - SD];

    shfbuf[i] = 0.f; shfbuf[FD + i] = 0.f;
    if (i < SD) shs[i] = 0.f;
    float hf = 0.f, hs = 0.f;
    float xg = g_xg[i], xp = g_xp[i], xd = g_xd[i];
    __syncwarp();

    const ulonglong2* hs2 = (const ulonglong2*)shs;

    for (int t = 0; t < T_STEPS; t++) {
        int p = (t & 1) << 5;
        float* rb = shfbuf + p;           // holds h_fast(t-1) final
        float* wb = shfbuf + (p ^ FD);
        const ulonglong2* rb2 = (const ulonglong2*)rb;
        const ulonglong2* wb2 = (const ulonglong2*)wb;

        // prefetch next step drives (hidden under this step's chain)
        float nxg = 0.f, nxp = 0.f, nxd = 0.f;
        if (t + 1 < T_STEPS) {
            nxg = g_xg[(t + 1) * FD + i];
            nxp = g_xp[(t + 1) * FD + i];
            nxd = g_xd[(t + 1) * FD + i];
        }

        // deferred slow-path matvec for step t-1 (reads h_fast(t-1), h_slow(t-2))
        float sacc = bs + dot48(ws2, rb2, hs2);
        // gate matvec for step t (independent — overlaps)
        float gacc = dot32(wgh2, rb2);

        float val = (i < SD) ? sig_f(sacc) : tanh_f(sacc);
        stmp[i] = val;
        float gate = sig_f(gacc + bgh + xg);
        hf = fmaf(gate, xp, hf);
        __syncwarp();                                   // S1: reads done, stmp visible

        if (i < SD) {
            float st = stmp[SD + i];
            float hn = (t == 0) ? 0.f : fmaf(0.02f * val, st - hs, hs);
            if (t > 0) g_h[(t - 1) * HD + FD + i] = hn;  // h_slow(t-1) for logits(t-1)
            hs = hn;
            shs[i] = hn;
        }
        wb[i] = hf;
        __syncwarp();                                   // S2: new h_fast + h_slow visible

        float sdrive = dot16(wfs2, hs2);                // W_fs @ h_slow(t-1)
        float cdr = bff + sdrive + xd;

        // relax 1: read wb, write rb
        {
            float u = dot32(wff2, wb2) + cdr;
            float tg = tanh_f(u);
            hf = fmaf(0.25f, tg - hf, hf);
            rb[i] = hf;
            __syncwarp();                               // S3
        }
        // relax 2: read rb, write wb (next iteration's read buffer)
        {
            float u = dot32(wff2, rb2) + cdr;
            float tg = tanh_f(u);
            hf = fmaf(0.25f, tg - hf, hf);
            wb[i] = hf;
            __syncwarp();                               // S4
        }
        g_h[t * HD + i] = hf;                           // fast part of state t
        xg = nxg; xp = nxp; xd = nxd;
    }

    // final deferred slow update for t = T-1 (h_fast final lives at offset 0)
    {
        const ulonglong2* rb2 = (const ulonglong2*)shfbuf;
        float sacc = bs + dot48(ws2, rb2, hs2);
        float val = (i < SD) ? sig_f(sacc) : tanh_f(sacc);
        stmp[i] = val;
        __syncwarp();
        if (i < SD) {
            float st = stmp[SD + i];
            float hn = fmaf(0.02f * val, st - hs, hs);
            g_h[(T_STEPS - 1) * HD + FD + i] = hn;
        }
    }
}

// ============================================================
// K3: output head — partial sumexp, f32x2 packed (24 FFMA2 + 12 LDS.128
// per (v,t) instead of 48 FFMA). No max needed: |logit| <= ~0.4.
// ============================================================
__global__ void __launch_bounds__(256) head_kernel(const float* __restrict__ Wout,
                                                   const float* __restrict__ bout)
{
    int vb = blockIdx.x;
    int tb = blockIdx.y;
    int tid = threadIdx.x;

    __shared__ __align__(16) float hsh[TT][HD];
    const float* hsrc = g_h + (size_t)tb * TT * HD;
    for (int k = tid; k < TT * HD; k += 256)
        ((float*)hsh)[k] = hsrc[k];
    __syncthreads();

    float acc[TT];
#pragma unroll
    for (int q = 0; q < TT; q++) acc[q] = 0.f;

    for (int vi = 0; vi < VBLOCK / 256; vi++) {
        int v = vb * VBLOCK + vi * 256 + tid;
        if (v < VOCAB) {
            ull w2[24];
            const ulonglong2* wp = (const ulonglong2*)(Wout + (size_t)v * HD);
#pragma unroll
            for (int q = 0; q < 12; q++) { ulonglong2 t4 = wp[q]; w2[2 * q] = t4.x; w2[2 * q + 1] = t4.y; }
            ull bo2 = pack2(bout[v], 0.f);
#pragma unroll 2
            for (int tt = 0; tt < TT; tt++) {
                const ulonglong2* hp = (const ulonglong2*)hsh[tt];
                ull a0 = bo2, a1 = 0, a2 = 0, a3 = 0;
#pragma unroll
                for (int m = 0; m < 12; m++) {
                    ulonglong2 pp = hp[m];
                    if (m & 1) { FMA2(a2, w2[2 * m], pp.x); FMA2(a3, w2[2 * m + 1], pp.y); }
                    else       { FMA2(a0, w2[2 * m], pp.x); FMA2(a1, w2[2 * m + 1], pp.y); }
                }
                acc[tt] += __expf(redu4(a0, a1, a2, a3));
            }
        }
    }

    // block reduction: warp shuffles then cross-warp shared combine
    __shared__ float swarp[8][TT];
    int lane = tid & 31, wrp = tid >> 5;
#pragma unroll
    for (int tt = 0; tt < TT; tt++) {
        float v = acc[tt];
        v += __shfl_xor_sync(0xffffffff, v, 16);
        v += __shfl_xor_sync(0xffffffff, v, 8);
        v += __shfl_xor_sync(0xffffffff, v, 4);
        v += __shfl_xor_sync(0xffffffff, v, 2);
        v += __shfl_xor_sync(0xffffffff, v, 1);
        if (lane == 0) swarp[wrp][tt] = v;
    }
    __syncthreads();
    if (tid < TT) {
        float s = 0.f;
#pragma unroll
        for (int q = 0; q < 8; q++) s += swarp[q][tid];
        g_partial[(size_t)vb * T_STEPS + tb * TT + tid] = s;
    }
}

// ============================================================
// K4: per-timestep NLL = log(sumexp) - target_logit
// ============================================================
__global__ void nll_kernel(const int* __restrict__ tok,
                           const float* __restrict__ Wout,
                           const float* __restrict__ bout)
{
    int t = blockIdx.x * blockDim.x + threadIdx.x;
    if (t >= T_STEPS) return;
    float s = 0.f;
#pragma unroll
    for (int vb = 0; vb < NVB; vb++) s += g_partial[(size_t)vb * T_STEPS + t];
    int tgt = tok[t + 1];
    const float* wrow = Wout + (size_t)tgt * HD;
    const float* hr = g_h + t * HD;
    float a = bout[tgt];
#pragma unroll
    for (int k = 0; k < HD; k++) a = fmaf(wrow[k], hr[k], a);
    g_nll[t] = logf(s) - a;
}

// ============================================================
// K5: deterministic mean reduction
// ============================================================
__global__ void reduce_kernel(float* __restrict__ out)
{
    __shared__ float sh[256];
    int tid = threadIdx.x;
    float s = 0.f;
    for (int t = tid; t < T_STEPS; t += 256) s += g_nll[t];
    sh[tid] = s;
    __syncthreads();
    for (int st = 128; st > 0; st >>= 1) {
        if (tid < st) sh[tid] += sh[tid + st];
        __syncthreads();
    }
    if (tid == 0) out[0] = sh[0] / (float)T_STEPS;
}

// ============================================================
extern "C" void kernel_launch(void* const* d_in, const int* in_sizes, int n_in,
                              void* d_out, int out_size)
{
    const int*   tok   = (const int*)  d_in[0];   // token_ids [4097]
    const float* embed = (const float*)d_in[1];   // [VOCAB, 32]
    const float* Wgh   = (const float*)d_in[2];   // W_gate_h [32,32]
    const float* bgh   = (const float*)d_in[3];
    const float* Wgx   = (const float*)d_in[4];   // W_gate_x
    const float* Wxp   = (const float*)d_in[5];   // W_x_proj
    const float* Wff   = (const float*)d_in[6];
    const float* bff   = (const float*)d_in[7];
    const float* Wfs   = (const float*)d_in[8];   // [32,16]
    const float* Wxf   = (const float*)d_in[9];   // W_x_fast
    const float* Wsgf  = (const float*)d_in[10];  // [16,32]
    const float* bsgf  = (const float*)d_in[11];
    const float* Wsgs  = (const float*)d_in[12];  // [16,16]
    const float* Wss   = (const float*)d_in[13];  // [16,16]
    const float* bss   = (const float*)d_in[14];
    const float* Wsf   = (const float*)d_in[15];  // [16,32]
    const float* Wout  = (const float*)d_in[16];  // [VOCAB,48]
    const float* bout  = (const float*)d_in[17];

    precompute_kernel<<<T_STEPS, 32>>>(tok, embed, Wgx, Wxp, Wxf);
    scan_kernel<<<1, 32>>>(Wgh, bgh, Wff, bff, Wfs, Wsgf, bsgf, Wsgs, Wss, bss, Wsf);
    dim3 g3(NVB, NTB);
    head_kernel<<<g3, 256>>>(Wout, bout);
    nll_kernel<<<32, 128>>>(tok, Wout, bout);
    reduce_kernel<<<1, 256>>>((float*)d_out);
}

// round 3
// speedup vs baseline: 2.1256x; 1.8379x over previous
#include <cuda_runtime.h>
#include <cuda_bf16.h>
#include <math.h>

#define T_STEPS 4096
#define FD 32
#define SD 16
#define HD 48
#define VOCAB 50257

#define VBLOCK 2048
#define NVB 25
#define TT 32
#define NTB 128
#define TILES (NVB * NTB)
#define NBLK 148

typedef unsigned long long ull;

// ---------------- scratch ----------------
__device__ float g_xg[T_STEPS * FD];
__device__ float g_xp[T_STEPS * FD];
__device__ float g_xd[T_STEPS * FD];
__device__ float g_h [T_STEPS * HD];
__device__ float g_partial[NVB * T_STEPS];
__device__ int g_prog;   // completed h rows
__device__ int g_tile;   // head tile queue
__device__ int g_done;   // completed head tiles

// ---------------- f32x2 packed helpers ----------------
#define FMA2(acc, a, b) asm("fma.rn.f32x2 %0, %1, %2, %0;" : "+l"(acc) : "l"(a), "l"(b))
#define ADD2(d, a, b)   asm("add.rn.f32x2 %0, %1, %2;"     : "=l"(d)   : "l"(a), "l"(b))
#define WFENCE()        asm volatile("" ::: "memory")

__device__ __forceinline__ ull pack2(float lo, float hi) {
    ull r; asm("mov.b64 %0, {%1, %2};" : "=l"(r) : "f"(lo), "f"(hi)); return r;
}
__device__ __forceinline__ float redu4(ull a0, ull a1, ull a2, ull a3) {
    ull s0, s1;
    ADD2(s0, a0, a1); ADD2(s1, a2, a3); ADD2(s0, s0, s1);
    float lo, hi; asm("mov.b64 {%0, %1}, %2;" : "=f"(lo), "=f"(hi) : "l"(s0));
    return lo + hi;
}
__device__ __forceinline__ float tanh_f(float x) {
    float r; asm("tanh.approx.f32 %0, %1;" : "=f"(r) : "f"(x)); return r;
}
__device__ __forceinline__ float sig_f(float x) {
    return fmaf(0.5f, tanh_f(0.5f * x), 0.5f);
}
__device__ __forceinline__ void publish(int v) {
    asm volatile("st.release.gpu.b32 [%0], %1;" :: "l"(&g_prog), "r"(v) : "memory");
}
__device__ __forceinline__ int load_prog() {
    int v; asm volatile("ld.acquire.gpu.b32 %0, [%1];" : "=r"(v) : "l"(&g_prog) : "memory");
    return v;
}

__device__ __forceinline__ float dot32(const ull* w2, const ulonglong2* h2) {
    ull a0 = 0, a1 = 0, a2 = 0, a3 = 0;
#pragma unroll
    for (int m = 0; m < 8; m++) {
        ulonglong2 pp = h2[m];
        if (m & 1) { FMA2(a2, w2[2 * m], pp.x); FMA2(a3, w2[2 * m + 1], pp.y); }
        else       { FMA2(a0, w2[2 * m], pp.x); FMA2(a1, w2[2 * m + 1], pp.y); }
    }
    return redu4(a0, a1, a2, a3);
}
__device__ __forceinline__ float dot16(const ull* w2, const ulonglong2* h2) {
    ull a0 = 0, a1 = 0, a2 = 0, a3 = 0;
#pragma unroll
    for (int m = 0; m < 4; m++) {
        ulonglong2 pp = h2[m];
        if (m & 1) { FMA2(a2, w2[2 * m], pp.x); FMA2(a3, w2[2 * m + 1], pp.y); }
        else       { FMA2(a0, w2[2 * m], pp.x); FMA2(a1, w2[2 * m + 1], pp.y); }
    }
    return redu4(a0, a1, a2, a3);
}
__device__ __forceinline__ float dot48(const ull* w2, const ulonglong2* hf2,
                                       const ulonglong2* hs2) {
    ull a0 = 0, a1 = 0, a2 = 0, a3 = 0;
#pragma unroll
    for (int m = 0; m < 8; m++) {
        ulonglong2 pp = hf2[m];
        if (m & 1) { FMA2(a2, w2[2 * m], pp.x); FMA2(a3, w2[2 * m + 1], pp.y); }
        else       { FMA2(a0, w2[2 * m], pp.x); FMA2(a1, w2[2 * m + 1], pp.y); }
    }
#pragma unroll
    for (int m = 0; m < 4; m++) {
        ulonglong2 pp = hs2[m];
        if (m & 1) { FMA2(a2, w2[16 + 2 * m], pp.x); FMA2(a3, w2[16 + 2 * m + 1], pp.y); }
        else       { FMA2(a0, w2[16 + 2 * m], pp.x); FMA2(a1, w2[16 + 2 * m + 1], pp.y); }
    }
    return redu4(a0, a1, a2, a3);
}

// ============================================================
// K1: precompute drives + reset coordination state
// ============================================================
__global__ void precompute_kernel(const int* __restrict__ tok,
                                  const float* __restrict__ embed,
                                  const float* __restrict__ Wgx,
                                  const float* __restrict__ Wxp,
                                  const float* __restrict__ Wxf)
{
    int t = blockIdx.x;
    int i = threadIdx.x;
    if (t == 0 && i == 0) { g_prog = 0; g_tile = 0; g_done = 0; }
    __shared__ __align__(16) float xs[FD];
    int tk = tok[t];
    xs[i] = embed[(size_t)tk * FD + i];
    __syncwarp();
    const ulonglong2* x2 = (const ulonglong2*)xs;
    const ull* pg = (const ull*)(Wgx + (size_t)i * FD);
    const ull* pp = (const ull*)(Wxp + (size_t)i * FD);
    const ull* pf = (const ull*)(Wxf + (size_t)i * FD);
    ull wg[16], wp[16], wf[16];
#pragma unroll
    for (int q = 0; q < 16; q++) { wg[q] = pg[q]; wp[q] = pp[q]; wf[q] = pf[q]; }
    g_xg[t * FD + i] = dot32(wg, x2);
    g_xp[t * FD + i] = dot32(wp, x2);
    g_xd[t * FD + i] = dot32(wf, x2);
}

// ============================================================
// scan body — one warp (block 0), publishes progress
// ============================================================
__device__ void scan_body(int i,
    const float* __restrict__ Wgh, const float* __restrict__ bgh_p,
    const float* __restrict__ Wff, const float* __restrict__ bff_p,
    const float* __restrict__ Wfs,
    const float* __restrict__ Wsgf, const float* __restrict__ bsgf,
    const float* __restrict__ Wsgs,
    const float* __restrict__ Wss, const float* __restrict__ bss,
    const float* __restrict__ Wsf)
{
    __shared__ __align__(16) float shfbuf[2 * FD];
    __shared__ __align__(16) float shs[SD];
    __shared__ __align__(16) float stmp[FD];

    ull wgh2[16], wff2[16], wfs2[8], ws2[24];
    {
        const ull* p0 = (const ull*)(Wgh + (size_t)i * FD);
        const ull* p1 = (const ull*)(Wff + (size_t)i * FD);
#pragma unroll
        for (int q = 0; q < 16; q++) { wgh2[q] = p0[q]; wff2[q] = p1[q]; }
        const ull* p2 = (const ull*)(Wfs + (size_t)i * SD);
#pragma unroll
        for (int q = 0; q < 8; q++) wfs2[q] = p2[q];
        if (i < SD) {
            const ull* pa = (const ull*)(Wsgf + (size_t)i * FD);
            const ull* pb = (const ull*)(Wsgs + (size_t)i * SD);
#pragma unroll
            for (int q = 0; q < 16; q++) ws2[q] = pa[q];
#pragma unroll
            for (int q = 0; q < 8; q++) ws2[16 + q] = pb[q];
        } else {
            const ull* pa = (const ull*)(Wsf + (size_t)(i - SD) * FD);
            const ull* pb = (const ull*)(Wss + (size_t)(i - SD) * SD);
#pragma unroll
            for (int q = 0; q < 16; q++) ws2[q] = pa[q];
#pragma unroll
            for (int q = 0; q < 8; q++) ws2[16 + q] = pb[q];
        }
    }
    float bgh = bgh_p[i];
    float bff = bff_p[i];
    float bs  = (i < SD) ? bsgf[i] : bss[i - SD];

    shfbuf[i] = 0.f; shfbuf[FD + i] = 0.f;
    if (i < SD) shs[i] = 0.f;
    float hf = 0.f, hs = 0.f;
    __syncwarp();

    const ulonglong2* hs2 = (const ulonglong2*)shs;

    // 4-step-ahead drive prefetch (coalesced, front-batched)
    float cg[4], cp[4], cd[4];
#pragma unroll
    for (int k = 0; k < 4; k++) {
        cg[k] = g_xg[k * FD + i];
        cp[k] = g_xp[k * FD + i];
        cd[k] = g_xd[k * FD + i];
    }

    for (int tg = 0; tg < T_STEPS / 4; tg++) {
        float ng[4], np[4], nd[4];
        if (tg + 1 < T_STEPS / 4) {
            int tb = (4 * tg + 4) * FD + i;
#pragma unroll
            for (int k = 0; k < 4; k++) {
                ng[k] = g_xg[tb + k * FD];
                np[k] = g_xp[tb + k * FD];
                nd[k] = g_xd[tb + k * FD];
            }
        } else {
#pragma unroll
            for (int k = 0; k < 4; k++) { ng[k] = 0.f; np[k] = 0.f; nd[k] = 0.f; }
        }

#pragma unroll
        for (int k = 0; k < 4; k++) {
            int t = 4 * tg + k;
            int p = (t & 1) << 5;
            float* rb = shfbuf + p;            // h_fast(t-1)
            float* wb = shfbuf + (p ^ FD);
            const ulonglong2* rb2 = (const ulonglong2*)rb;
            const ulonglong2* wb2 = (const ulonglong2*)wb;
            float xg = cg[k], xp = cp[k], xd = cd[k];

            // deferred slow matvec (t-1) + gate matvec (t), both on rb
            float sacc = bs + dot48(ws2, rb2, hs2);
            float gacc = dot32(wgh2, rb2);

            float val = (i < SD) ? sig_f(sacc) : tanh_f(sacc);
            stmp[i] = val;
            float gate = sig_f(gacc + bgh + xg);
            hf = fmaf(gate, xp, hf);
            WFENCE();                                    // S1

            if (i < SD) {
                float st = stmp[SD + i];
                float hn = (t == 0) ? 0.f : fmaf(0.02f * val, st - hs, hs);
                if (t > 0) g_h[(t - 1) * HD + FD + i] = hn;
                hs = hn;
                shs[i] = hn;
            }
            wb[i] = hf;
            WFENCE();                                    // S2

            float sdrive = dot16(wfs2, hs2);
            float cdr = bff + sdrive + xd;
            {
                float u = dot32(wff2, wb2) + cdr;
                float tg_ = tanh_f(u);
                hf = fmaf(0.25f, tg_ - hf, hf);
                rb[i] = hf;
                WFENCE();                                // S3
            }
            {
                float u = dot32(wff2, rb2) + cdr;
                float tg_ = tanh_f(u);
                hf = fmaf(0.25f, tg_ - hf, hf);
                wb[i] = hf;
                WFENCE();                                // S4
            }
            g_h[t * HD + i] = hf;
        }
#pragma unroll
        for (int k = 0; k < 4; k++) { cg[k] = ng[k]; cp[k] = np[k]; cd[k] = nd[k]; }

        if ((tg & 7) == 7) {                             // every 32 steps
            __syncwarp();
            if (i == 0) publish(4 * tg + 3);
        }
    }

    // final deferred slow update for t = T-1 (final h_fast at offset 0)
    {
        const ulonglong2* rb2 = (const ulonglong2*)shfbuf;
        float sacc = bs + dot48(ws2, rb2, hs2);
        float val = (i < SD) ? sig_f(sacc) : tanh_f(sacc);
        stmp[i] = val;
        WFENCE();
        if (i < SD) {
            float st = stmp[SD + i];
            float hn = fmaf(0.02f * val, st - hs, hs);
            g_h[(T_STEPS - 1) * HD + FD + i] = hn;
        }
        __syncwarp();
        if (i == 0) publish(T_STEPS);
    }
}

// ============================================================
// head tile — one (vb, tb) partial-sumexp tile (256 threads)
// ============================================================
__device__ void head_tile(int vb, int tb,
                          const float* __restrict__ Wout,
                          const float* __restrict__ bout)
{
    int tid = threadIdx.x;
    __shared__ __align__(16) float hsh[TT][HD];
    const float* hsrc = g_h + (size_t)tb * TT * HD;
    for (int k = tid; k < TT * HD; k += 256)
        ((float*)hsh)[k] = hsrc[k];
    __syncthreads();

    float acc[TT];
#pragma unroll
    for (int q = 0; q < TT; q++) acc[q] = 0.f;

    for (int vi = 0; vi < VBLOCK / 256; vi++) {
        int v = vb * VBLOCK + vi * 256 + tid;
        if (v < VOCAB) {
            ull w2[24];
            const ulonglong2* wp = (const ulonglong2*)(Wout + (size_t)v * HD);
#pragma unroll
            for (int q = 0; q < 12; q++) {
                ulonglong2 t4 = wp[q]; w2[2 * q] = t4.x; w2[2 * q + 1] = t4.y;
            }
            ull bo2 = pack2(bout[v], 0.f);
#pragma unroll 2
            for (int tt = 0; tt < TT; tt++) {
                const ulonglong2* hp = (const ulonglong2*)hsh[tt];
                ull a0 = bo2, a1 = 0, a2 = 0, a3 = 0;
#pragma unroll
                for (int m = 0; m < 12; m++) {
                    ulonglong2 pp = hp[m];
                    if (m & 1) { FMA2(a2, w2[2 * m], pp.x); FMA2(a3, w2[2 * m + 1], pp.y); }
                    else       { FMA2(a0, w2[2 * m], pp.x); FMA2(a1, w2[2 * m + 1], pp.y); }
                }
                acc[tt] += __expf(redu4(a0, a1, a2, a3));
            }
        }
    }

    __shared__ float swarp[8][TT];
    int lane = tid & 31, wrp = tid >> 5;
#pragma unroll
    for (int tt = 0; tt < TT; tt++) {
        float v = acc[tt];
        v += __shfl_xor_sync(0xffffffff, v, 16);
        v += __shfl_xor_sync(0xffffffff, v, 8);
        v += __shfl_xor_sync(0xffffffff, v, 4);
        v += __shfl_xor_sync(0xffffffff, v, 2);
        v += __shfl_xor_sync(0xffffffff, v, 1);
        if (lane == 0) swarp[wrp][tt] = v;
    }
    __syncthreads();
    if (tid < TT) {
        float s = 0.f;
#pragma unroll
        for (int q = 0; q < 8; q++) s += swarp[q][tid];
        g_partial[(size_t)vb * T_STEPS + tb * TT + tid] = s;
    }
    __syncthreads();
}

// ============================================================
// finale — NLL + mean (run by the block finishing the last tile)
// ============================================================
__device__ void finale(const int* __restrict__ tok,
                       const float* __restrict__ Wout,
                       const float* __restrict__ bout,
                       float* __restrict__ out)
{
    int tid = threadIdx.x;
    float local = 0.f;
    for (int t = tid; t < T_STEPS; t += 256) {
        float s = 0.f;
#pragma unroll
        for (int vb = 0; vb < NVB; vb++) s += g_partial[(size_t)vb * T_STEPS + t];
        int tgt = tok[t + 1];
        const float* wr = Wout + (size_t)tgt * HD;
        const float* hr = g_h + t * HD;
        float a = bout[tgt];
#pragma unroll
        for (int k = 0; k < HD; k++) a = fmaf(wr[k], hr[k], a);
        local += logf(s) - a;
    }
    __shared__ float red[256];
    red[tid] = local;
    __syncthreads();
    for (int st = 128; st > 0; st >>= 1) {
        if (tid < st) red[tid] += red[tid + st];
        __syncthreads();
    }
    if (tid == 0) out[0] = red[0] / (float)T_STEPS;
}

// ============================================================
// fused persistent kernel
// ============================================================
__global__ void __launch_bounds__(256, 1) fused_kernel(
    const int* __restrict__ tok,
    const float* __restrict__ Wgh, const float* __restrict__ bgh,
    const float* __restrict__ Wff, const float* __restrict__ bff,
    const float* __restrict__ Wfs,
    const float* __restrict__ Wsgf, const float* __restrict__ bsgf,
    const float* __restrict__ Wsgs,
    const float* __restrict__ Wss, const float* __restrict__ bss,
    const float* __restrict__ Wsf,
    const float* __restrict__ Wout, const float* __restrict__ bout,
    float* __restrict__ out)
{
    int tid = threadIdx.x;

    if (blockIdx.x == 0) {
        if (tid < 32)
            scan_body(tid, Wgh, bgh, Wff, bff, Wfs, Wsgf, bsgf, Wsgs, Wss, bss, Wsf);
        return;
    }

    __shared__ int s_tile;
    __shared__ int s_flag;
    for (;;) {
        if (tid == 0) s_tile = atomicAdd(&g_tile, 1);
        __syncthreads();
        int tile = s_tile;
        if (tile >= TILES) break;
        int tb = tile / NVB;
        int vb = tile - tb * NVB;

        if (tid == 0) {
            int need = (tb + 1) * TT;
            while (load_prog() < need) __nanosleep(64);
        }
        __syncthreads();

        head_tile(vb, tb, Wout, bout);

        if (tid == 0) {
            __threadfence();
            int d = atomicAdd(&g_done, 1);
            s_flag = (d == TILES - 1);
        }
        __syncthreads();
        if (s_flag) {
            __threadfence();
            finale(tok, Wout, bout, out);
        }
        __syncthreads();
    }
}

// ============================================================
extern "C" void kernel_launch(void* const* d_in, const int* in_sizes, int n_in,
                              void* d_out, int out_size)
{
    const int*   tok   = (const int*)  d_in[0];
    const float* embed = (const float*)d_in[1];
    const float* Wgh   = (const float*)d_in[2];
    const float* bgh   = (const float*)d_in[3];
    const float* Wgx   = (const float*)d_in[4];
    const float* Wxp   = (const float*)d_in[5];
    const float* Wff   = (const float*)d_in[6];
    const float* bff   = (const float*)d_in[7];
    const float* Wfs   = (const float*)d_in[8];
    const float* Wxf   = (const float*)d_in[9];
    const float* Wsgf  = (const float*)d_in[10];
    const float* bsgf  = (const float*)d_in[11];
    const float* Wsgs  = (const float*)d_in[12];
    const float* Wss   = (const float*)d_in[13];
    const float* bss   = (const float*)d_in[14];
    const float* Wsf   = (const float*)d_in[15];
    const float* Wout  = (const float*)d_in[16];
    const float* bout  = (const float*)d_in[17];

    precompute_kernel<<<T_STEPS, 32>>>(tok, embed, Wgx, Wxp, Wxf);
    fused_kernel<<<NBLK, 256>>>(tok, Wgh, bgh, Wff, bff, Wfs,
                                Wsgf, bsgf, Wsgs, Wss, bss, Wsf,
                                Wout, bout, (float*)d_out);
}

// round 4
// speedup vs baseline: 2.2302x; 1.0492x over previous
#include <cuda_runtime.h>
#include <cuda_bf16.h>
#include <math.h>

#define T_STEPS 4096
#define FD 32
#define SD 16
#define HD 48
#define VOCAB 50257

#define VBLOCK 2048
#define NVB 25
#define TT 32
#define NTB 128
#define TILES (NVB * NTB)
#define NBLK 148

typedef unsigned long long ull;

// ---------------- scratch ----------------
__device__ float g_xg[T_STEPS * FD];   // 0.5 * (W_gate_x @ x)
__device__ float g_xp[T_STEPS * FD];   // 0.5 * (W_x_proj @ x)
__device__ float g_xd[T_STEPS * FD];   // W_x_fast @ x
__device__ float g_h [T_STEPS * HD];
__device__ float g_partial[NVB * T_STEPS];
__device__ int g_prog;
__device__ int g_tile;
__device__ int g_done;

// ---------------- helpers ----------------
#define FMA2(acc, a, b) asm("fma.rn.f32x2 %0, %1, %2, %0;" : "+l"(acc) : "l"(a), "l"(b))
#define ADD2(d, a, b)   asm("add.rn.f32x2 %0, %1, %2;"     : "=l"(d)   : "l"(a), "l"(b))
#define WFENCE()        asm volatile("" ::: "memory")
#define BAR64()         asm volatile("bar.sync 1, 64;" ::: "memory")

__device__ __forceinline__ ull pack2(float lo, float hi) {
    ull r; asm("mov.b64 %0, {%1, %2};" : "=l"(r) : "f"(lo), "f"(hi)); return r;
}
__device__ __forceinline__ float redu4(ull a0, ull a1, ull a2, ull a3) {
    ull s0, s1;
    ADD2(s0, a0, a1); ADD2(s1, a2, a3); ADD2(s0, s0, s1);
    float lo, hi; asm("mov.b64 {%0, %1}, %2;" : "=f"(lo), "=f"(hi) : "l"(s0));
    return lo + hi;
}
__device__ __forceinline__ float tanh_f(float x) {
    float r; asm("tanh.approx.f32 %0, %1;" : "=f"(r) : "f"(x)); return r;
}
__device__ __forceinline__ float sig_f(float x) {
    return fmaf(0.5f, tanh_f(0.5f * x), 0.5f);
}
__device__ __forceinline__ void publish(int v) {
    asm volatile("st.release.gpu.b32 [%0], %1;" :: "l"(&g_prog), "r"(v) : "memory");
}
__device__ __forceinline__ int load_prog() {
    int v; asm volatile("ld.acquire.gpu.b32 %0, [%1];" : "=r"(v) : "l"(&g_prog) : "memory");
    return v;
}

__device__ __forceinline__ float dot32(const ull* w2, const ulonglong2* h2) {
    ull a0 = 0, a1 = 0, a2 = 0, a3 = 0;
#pragma unroll
    for (int m = 0; m < 8; m++) {
        ulonglong2 pp = h2[m];
        if (m & 1) { FMA2(a2, w2[2 * m], pp.x); FMA2(a3, w2[2 * m + 1], pp.y); }
        else       { FMA2(a0, w2[2 * m], pp.x); FMA2(a1, w2[2 * m + 1], pp.y); }
    }
    return redu4(a0, a1, a2, a3);
}
__device__ __forceinline__ float dot16(const ull* w2, const ulonglong2* h2) {
    ull a0 = 0, a1 = 0, a2 = 0, a3 = 0;
#pragma unroll
    for (int m = 0; m < 4; m++) {
        ulonglong2 pp = h2[m];
        if (m & 1) { FMA2(a2, w2[2 * m], pp.x); FMA2(a3, w2[2 * m + 1], pp.y); }
        else       { FMA2(a0, w2[2 * m], pp.x); FMA2(a1, w2[2 * m + 1], pp.y); }
    }
    return redu4(a0, a1, a2, a3);
}

// ============================================================
// K1: precompute drives (xg, xp pre-halved for sigmoid folding)
// ============================================================
__global__ void precompute_kernel(const int* __restrict__ tok,
                                  const float* __restrict__ embed,
                                  const float* __restrict__ Wgx,
                                  const float* __restrict__ Wxp,
                                  const float* __restrict__ Wxf)
{
    int t = blockIdx.x;
    int i = threadIdx.x;
    if (t == 0 && i == 0) { g_prog = 0; g_tile = 0; g_done = 0; }
    __shared__ __align__(16) float xs[FD];
    int tk = tok[t];
    xs[i] = embed[(size_t)tk * FD + i];
    __syncwarp();
    const ulonglong2* x2 = (const ulonglong2*)xs;
    const ull* pg = (const ull*)(Wgx + (size_t)i * FD);
    const ull* pp = (const ull*)(Wxp + (size_t)i * FD);
    const ull* pf = (const ull*)(Wxf + (size_t)i * FD);
    ull wg[16], wp[16], wf[16];
#pragma unroll
    for (int q = 0; q < 16; q++) { wg[q] = pg[q]; wp[q] = pp[q]; wf[q] = pf[q]; }
    g_xg[t * FD + i] = 0.5f * dot32(wg, x2);
    g_xp[t * FD + i] = 0.5f * dot32(wp, x2);
    g_xd[t * FD + i] = dot32(wf, x2);
}

// ---------------- block-0 shared state for the scan ----------------
// (declared inside fused kernel; passed by pointer)
struct ScanSmem {
    float hfin[2][FD];   // final h_fast per step parity (warp0 writes)
    float wk0[FD];       // warp0 private relax buffers
    float wk1[FD];
    float shs[SD];       // h_slow (warp1 writes)
};

// ============================================================
// warp0: gate + relax (fast-state critical path only)
// ============================================================
__device__ void scan_warp0(int i, ScanSmem* S,
    const float* __restrict__ Wgh, const float* __restrict__ bgh_p,
    const float* __restrict__ Wff, const float* __restrict__ bff_p,
    const float* __restrict__ Wfs)
{
    ull wghH2[16], wff2[16], wfs2[8];
#pragma unroll
    for (int q = 0; q < 16; q++) {
        wghH2[q] = pack2(0.5f * Wgh[i * FD + 2 * q], 0.5f * Wgh[i * FD + 2 * q + 1]);
    }
    {
        const ull* p1 = (const ull*)(Wff + (size_t)i * FD);
#pragma unroll
        for (int q = 0; q < 16; q++) wff2[q] = p1[q];
        const ull* p2 = (const ull*)(Wfs + (size_t)i * SD);
#pragma unroll
        for (int q = 0; q < 8; q++) wfs2[q] = p2[q];
    }
    float bghH = 0.5f * bgh_p[i];
    float bff  = bff_p[i];

    S->hfin[0][i] = 0.f; S->hfin[1][i] = 0.f;
    float hf = 0.f;
    WFENCE();

    float cg[4], cp[4], cd[4];
#pragma unroll
    for (int k = 0; k < 4; k++) {
        cg[k] = g_xg[k * FD + i];
        cp[k] = g_xp[k * FD + i];
        cd[k] = g_xd[k * FD + i];
    }

    const ulonglong2* shs2 = (const ulonglong2*)S->shs;

    for (int tg = 0; tg < T_STEPS / 4; tg++) {
        float ng[4], np[4], nd[4];
        if (tg + 1 < T_STEPS / 4) {
            int tb = (4 * tg + 4) * FD + i;
#pragma unroll
            for (int k = 0; k < 4; k++) {
                ng[k] = g_xg[tb + k * FD];
                np[k] = g_xp[tb + k * FD];
                nd[k] = g_xd[tb + k * FD];
            }
        } else {
#pragma unroll
            for (int k = 0; k < 4; k++) { ng[k] = 0.f; np[k] = 0.f; nd[k] = 0.f; }
        }

#pragma unroll
        for (int k = 0; k < 4; k++) {
            int t = 4 * tg + k;
            const ulonglong2* hp2 = (const ulonglong2*)S->hfin[(t + 1) & 1];

            BAR64();                                   // A: hand h_fast(t-1) to warp1

            // gate stage (all operands warp0-local; LDS issues immediately)
            float gd = dot32(wghH2, hp2);
            float tv = tanh_f(gd + bghH + cg[k]);
            float base = hf + cp[k];
            hf = fmaf(cp[k], tv, base);
            S->wk0[i] = hf;
            WFENCE();
            // relax1 dot — issued before bar B, completes during wait
            float r1 = dot32(wff2, (const ulonglong2*)S->wk0);
            float bxd = bff + cd[k];
            float hf75 = 0.75f * hf;

            BAR64();                                   // B: h_slow(t-1) now visible

            float sdr = dot16(wfs2, shs2);             // W_fs @ h_slow(t-1)
            float tg1 = tanh_f(r1 + bxd + sdr);
            hf = fmaf(0.25f, tg1, hf75);
            S->wk1[i] = hf;
            WFENCE();
            float r2 = dot32(wff2, (const ulonglong2*)S->wk1);
            float hf75b = 0.75f * hf;
            float tg2 = tanh_f(r2 + bxd + sdr);
            hf = fmaf(0.25f, tg2, hf75b);
            S->hfin[t & 1][i] = hf;
            WFENCE();
        }
#pragma unroll
        for (int k = 0; k < 4; k++) { cg[k] = ng[k]; cp[k] = np[k]; cd[k] = nd[k]; }
    }
    BAR64();                                           // final handoff
}

// ============================================================
// warp1: slow-state update, g_h copies, progress publish
// ============================================================
__device__ void scan_warp1(int i, ScanSmem* S,
    const float* __restrict__ Wsgf, const float* __restrict__ bsgf,
    const float* __restrict__ Wsgs,
    const float* __restrict__ Wss, const float* __restrict__ bss,
    const float* __restrict__ Wsf)
{
    ull ws2[24];
    float bs;
    if (i < SD) {
        const ull* pa = (const ull*)(Wsgf + (size_t)i * FD);
        const ull* pb = (const ull*)(Wsgs + (size_t)i * SD);
#pragma unroll
        for (int q = 0; q < 16; q++) ws2[q] = pa[q];
#pragma unroll
        for (int q = 0; q < 8; q++) ws2[16 + q] = pb[q];
        bs = bsgf[i];
    } else {
        const ull* pa = (const ull*)(Wsf + (size_t)(i - SD) * FD);
        const ull* pb = (const ull*)(Wss + (size_t)(i - SD) * SD);
#pragma unroll
        for (int q = 0; q < 16; q++) ws2[q] = pa[q];
#pragma unroll
        for (int q = 0; q < 8; q++) ws2[16 + q] = pb[q];
        bs = bss[i - SD];
    }
    if (i < SD) S->shs[i] = 0.f;
    float hs = 0.f;
    WFENCE();

    const ulonglong2* shs2 = (const ulonglong2*)S->shs;

    for (int t = 0; t < T_STEPS; t++) {
        // h_slow(t-2) part of the slow matvec — warp1-own, pre-bar
        float ss = dot16(ws2 + 16, shs2);

        BAR64();                                       // A

        if (t > 0) {
            const float* hp = S->hfin[(t + 1) & 1];    // h_fast(t-1) final
            float ht = dot32(ws2, (const ulonglong2*)hp);
            float sacc = ss + ht + bs;
            float val = (i < SD) ? sig_f(sacc) : tanh_f(sacc);
            float prt = __shfl_xor_sync(0xffffffffu, val, 16);
            float hfl = hp[i];
            if (i < SD) {
                hs = fmaf(0.02f * val, prt - hs, hs);
                S->shs[i] = hs;
                g_h[(t - 1) * HD + FD + i] = hs;
            }
            g_h[(t - 1) * HD + i] = hfl;
            WFENCE();
        }

        BAR64();                                       // B

        if (((t & 31) == 0) && t > 0 && i == 0) publish(t);
    }

    BAR64();                                           // final
    // slow update + copy for row T-1
    {
        float ss = dot16(ws2 + 16, shs2);
        const float* hp = S->hfin[(T_STEPS - 1) & 1];
        float ht = dot32(ws2, (const ulonglong2*)hp);
        float sacc = ss + ht + bs;
        float val = (i < SD) ? sig_f(sacc) : tanh_f(sacc);
        float prt = __shfl_xor_sync(0xffffffffu, val, 16);
        float hfl = hp[i];
        if (i < SD) {
            hs = fmaf(0.02f * val, prt - hs, hs);
            g_h[(T_STEPS - 1) * HD + FD + i] = hs;
        }
        g_h[(T_STEPS - 1) * HD + i] = hfl;
        __syncwarp();
        if (i == 0) publish(T_STEPS);
    }
}

// ============================================================
// head tile — one (vb, tb) partial-sumexp tile (256 threads)
// ============================================================
__device__ void head_tile(int vb, int tb,
                          const float* __restrict__ Wout,
                          const float* __restrict__ bout)
{
    int tid = threadIdx.x;
    __shared__ __align__(16) float hsh[TT][HD];
    const float* hsrc = g_h + (size_t)tb * TT * HD;
    for (int k = tid; k < TT * HD; k += 256)
        ((float*)hsh)[k] = hsrc[k];
    __syncthreads();

    float acc[TT];
#pragma unroll
    for (int q = 0; q < TT; q++) acc[q] = 0.f;

    for (int vi = 0; vi < VBLOCK / 256; vi++) {
        int v = vb * VBLOCK + vi * 256 + tid;
        if (v < VOCAB) {
            ull w2[24];
            const ulonglong2* wp = (const ulonglong2*)(Wout + (size_t)v * HD);
#pragma unroll
            for (int q = 0; q < 12; q++) {
                ulonglong2 t4 = wp[q]; w2[2 * q] = t4.x; w2[2 * q + 1] = t4.y;
            }
            ull bo2 = pack2(bout[v], 0.f);
#pragma unroll 2
            for (int tt = 0; tt < TT; tt++) {
                const ulonglong2* hp = (const ulonglong2*)hsh[tt];
                ull a0 = bo2, a1 = 0, a2 = 0, a3 = 0;
#pragma unroll
                for (int m = 0; m < 12; m++) {
                    ulonglong2 pp = hp[m];
                    if (m & 1) { FMA2(a2, w2[2 * m], pp.x); FMA2(a3, w2[2 * m + 1], pp.y); }
                    else       { FMA2(a0, w2[2 * m], pp.x); FMA2(a1, w2[2 * m + 1], pp.y); }
                }
                acc[tt] += __expf(redu4(a0, a1, a2, a3));
            }
        }
    }

    __shared__ float swarp[8][TT];
    int lane = tid & 31, wrp = tid >> 5;
#pragma unroll
    for (int tt = 0; tt < TT; tt++) {
        float v = acc[tt];
        v += __shfl_xor_sync(0xffffffff, v, 16);
        v += __shfl_xor_sync(0xffffffff, v, 8);
        v += __shfl_xor_sync(0xffffffff, v, 4);
        v += __shfl_xor_sync(0xffffffff, v, 2);
        v += __shfl_xor_sync(0xffffffff, v, 1);
        if (lane == 0) swarp[wrp][tt] = v;
    }
    __syncthreads();
    if (tid < TT) {
        float s = 0.f;
#pragma unroll
        for (int q = 0; q < 8; q++) s += swarp[q][tid];
        g_partial[(size_t)vb * T_STEPS + tb * TT + tid] = s;
    }
    __syncthreads();
}

// ============================================================
// finale — NLL + mean
// ============================================================
__device__ void finale(const int* __restrict__ tok,
                       const float* __restrict__ Wout,
                       const float* __restrict__ bout,
                       float* __restrict__ out)
{
    int tid = threadIdx.x;
    float local = 0.f;
    for (int t = tid; t < T_STEPS; t += 256) {
        float s = 0.f;
#pragma unroll
        for (int vb = 0; vb < NVB; vb++) s += g_partial[(size_t)vb * T_STEPS + t];
        int tgt = tok[t + 1];
        const float* wr = Wout + (size_t)tgt * HD;
        const float* hr = g_h + t * HD;
        float a = bout[tgt];
#pragma unroll
        for (int k = 0; k < HD; k++) a = fmaf(wr[k], hr[k], a);
        local += logf(s) - a;
    }
    __shared__ float red[256];
    red[tid] = local;
    __syncthreads();
    for (int st = 128; st > 0; st >>= 1) {
        if (tid < st) red[tid] += red[tid + st];
        __syncthreads();
    }
    if (tid == 0) out[0] = red[0] / (float)T_STEPS;
}

// ============================================================
// fused persistent kernel
// ============================================================
__global__ void __launch_bounds__(256, 1) fused_kernel(
    const int* __restrict__ tok,
    const float* __restrict__ Wgh, const float* __restrict__ bgh,
    const float* __restrict__ Wff, const float* __restrict__ bff,
    const float* __restrict__ Wfs,
    const float* __restrict__ Wsgf, const float* __restrict__ bsgf,
    const float* __restrict__ Wsgs,
    const float* __restrict__ Wss, const float* __restrict__ bss,
    const float* __restrict__ Wsf,
    const float* __restrict__ Wout, const float* __restrict__ bout,
    float* __restrict__ out)
{
    int tid = threadIdx.x;

    if (blockIdx.x == 0) {
        __shared__ __align__(16) ScanSmem S;
        int lane = tid & 31;
        if (tid < 32)
            scan_warp0(lane, &S, Wgh, bgh, Wff, bff, Wfs);
        else if (tid < 64)
            scan_warp1(lane, &S, Wsgf, bsgf, Wsgs, Wss, bss, Wsf);
        return;
    }

    __shared__ int s_tile;
    __shared__ int s_flag;
    for (;;) {
        if (tid == 0) s_tile = atomicAdd(&g_tile, 1);
        __syncthreads();
        int tile = s_tile;
        if (tile >= TILES) break;
        int tb = tile / NVB;
        int vb = tile - tb * NVB;

        if (tid == 0) {
            int need = (tb + 1) * TT;
            while (load_prog() < need) __nanosleep(64);
        }
        __syncthreads();

        head_tile(vb, tb, Wout, bout);

        if (tid == 0) {
            __threadfence();
            int d = atomicAdd(&g_done, 1);
            s_flag = (d == TILES - 1);
        }
        __syncthreads();
        if (s_flag) {
            __threadfence();
            finale(tok, Wout, bout, out);
        }
        __syncthreads();
    }
}

// ============================================================
extern "C" void kernel_launch(void* const* d_in, const int* in_sizes, int n_in,
                              void* d_out, int out_size)
{
    const int*   tok   = (const int*)  d_in[0];
    const float* embed = (const float*)d_in[1];
    const float* Wgh   = (const float*)d_in[2];
    const float* bgh   = (const float*)d_in[3];
    const float* Wgx   = (const float*)d_in[4];
    const float* Wxp   = (const float*)d_in[5];
    const float* Wff   = (const float*)d_in[6];
    const float* bff   = (const float*)d_in[7];
    const float* Wfs   = (const float*)d_in[8];
    const float* Wxf   = (const float*)d_in[9];
    const float* Wsgf  = (const float*)d_in[10];
    const float* bsgf  = (const float*)d_in[11];
    const float* Wsgs  = (const float*)d_in[12];
    const float* Wss   = (const float*)d_in[13];
    const float* bss   = (const float*)d_in[14];
    const float* Wsf   = (const float*)d_in[15];
    const float* Wout  = (const float*)d_in[16];
    const float* bout  = (const float*)d_in[17];

    precompute_kernel<<<T_STEPS, 32>>>(tok, embed, Wgx, Wxp, Wxf);
    fused_kernel<<<NBLK, 256>>>(tok, Wgh, bgh, Wff, bff, Wfs,
                                Wsgf, bsgf, Wsgs, Wss, bss, Wsf,
                                Wout, bout, (float*)d_out);
}

// round 5
// speedup vs baseline: 2.3573x; 1.0570x over previous
#include <cuda_runtime.h>
#include <cuda_bf16.h>
#include <math.h>

#define T_STEPS 4096
#define FD 32
#define SD 16
#define HD 48
#define VOCAB 50257

#define VBLOCK 2048
#define NVB 25
#define TT 32
#define NTB 128
#define TILES (NVB * NTB)
#define NBLK 148

typedef unsigned long long ull;

// ---------------- scratch ----------------
__device__ float g_xg[T_STEPS * FD];   // 0.5 * (W_gate_x @ x)
__device__ float g_xp[T_STEPS * FD];   // 0.5 * (W_x_proj @ x)
__device__ float g_xd[T_STEPS * FD];   // W_x_fast @ x
__device__ float g_h [T_STEPS * HD];
__device__ float g_partial[NVB * T_STEPS];
__device__ int g_prog;
__device__ int g_tile;
__device__ int g_done;

// ---------------- helpers ----------------
#define FMA2(acc, a, b) asm("fma.rn.f32x2 %0, %1, %2, %0;" : "+l"(acc) : "l"(a), "l"(b))
#define ADD2(d, a, b)   asm("add.rn.f32x2 %0, %1, %2;"     : "=l"(d)   : "l"(a), "l"(b))
#define WFENCE()        asm volatile("" ::: "memory")
// producer/consumer named barriers (CUTLASS NamedBarrier pattern)
#define ARRIVE_A() asm volatile("bar.arrive 1, 64;" ::: "memory")
#define SYNC_A()   asm volatile("bar.sync 1, 64;"   ::: "memory")
#define ARRIVE_B() asm volatile("bar.arrive 2, 64;" ::: "memory")
#define SYNC_B()   asm volatile("bar.sync 2, 64;"   ::: "memory")

__device__ __forceinline__ ull pack2(float lo, float hi) {
    ull r; asm("mov.b64 %0, {%1, %2};" : "=l"(r) : "f"(lo), "f"(hi)); return r;
}
__device__ __forceinline__ float redu2(ull a0, ull a1) {
    ull s; ADD2(s, a0, a1);
    float lo, hi; asm("mov.b64 {%0, %1}, %2;" : "=f"(lo), "=f"(hi) : "l"(s));
    return lo + hi;
}
__device__ __forceinline__ float redu4(ull a0, ull a1, ull a2, ull a3) {
    ull s0, s1;
    ADD2(s0, a0, a1); ADD2(s1, a2, a3); ADD2(s0, s0, s1);
    float lo, hi; asm("mov.b64 {%0, %1}, %2;" : "=f"(lo), "=f"(hi) : "l"(s0));
    return lo + hi;
}
__device__ __forceinline__ float tanh_f(float x) {
    float r; asm("tanh.approx.f32 %0, %1;" : "=f"(r) : "f"(x)); return r;
}
__device__ __forceinline__ float sig_f(float x) {
    return fmaf(0.5f, tanh_f(0.5f * x), 0.5f);
}
__device__ __forceinline__ void publish(int v) {
    asm volatile("st.release.gpu.b32 [%0], %1;" :: "l"(&g_prog), "r"(v) : "memory");
}
__device__ __forceinline__ int load_prog() {
    int v; asm volatile("ld.acquire.gpu.b32 %0, [%1];" : "=r"(v) : "l"(&g_prog) : "memory");
    return v;
}

// dot of 32 floats, 2 accumulators, bias pre-packed into accumulator init
__device__ __forceinline__ float dot32i(const ull* w2, const ulonglong2* h2, ull init) {
    ull a0 = init, a1 = 0;
#pragma unroll
    for (int m = 0; m < 8; m++) {
        ulonglong2 pp = h2[m];
        FMA2(a0, w2[2 * m], pp.x);
        FMA2(a1, w2[2 * m + 1], pp.y);
    }
    return redu2(a0, a1);
}
__device__ __forceinline__ float dot16i(const ull* w2, const ulonglong2* h2, ull init) {
    ull a0 = init, a1 = 0;
#pragma unroll
    for (int m = 0; m < 4; m++) {
        ulonglong2 pp = h2[m];
        FMA2(a0, w2[2 * m], pp.x);
        FMA2(a1, w2[2 * m + 1], pp.y);
    }
    return redu2(a0, a1);
}
__device__ __forceinline__ float dot32(const ull* w2, const ulonglong2* h2) {
    ull a0 = 0, a1 = 0, a2 = 0, a3 = 0;
#pragma unroll
    for (int m = 0; m < 8; m++) {
        ulonglong2 pp = h2[m];
        if (m & 1) { FMA2(a2, w2[2 * m], pp.x); FMA2(a3, w2[2 * m + 1], pp.y); }
        else       { FMA2(a0, w2[2 * m], pp.x); FMA2(a1, w2[2 * m + 1], pp.y); }
    }
    return redu4(a0, a1, a2, a3);
}

// ============================================================
// K1: precompute drives (xg, xp pre-halved for sigmoid folding)
// ============================================================
__global__ void precompute_kernel(const int* __restrict__ tok,
                                  const float* __restrict__ embed,
                                  const float* __restrict__ Wgx,
                                  const float* __restrict__ Wxp,
                                  const float* __restrict__ Wxf)
{
    int t = blockIdx.x;
    int i = threadIdx.x;
    if (t == 0 && i == 0) { g_prog = 0; g_tile = 0; g_done = 0; }
    __shared__ __align__(16) float xs[FD];
    int tk = tok[t];
    xs[i] = embed[(size_t)tk * FD + i];
    __syncwarp();
    const ulonglong2* x2 = (const ulonglong2*)xs;
    const ull* pg = (const ull*)(Wgx + (size_t)i * FD);
    const ull* pp = (const ull*)(Wxp + (size_t)i * FD);
    const ull* pf = (const ull*)(Wxf + (size_t)i * FD);
    ull wg[16], wp[16], wf[16];
#pragma unroll
    for (int q = 0; q < 16; q++) { wg[q] = pg[q]; wp[q] = pp[q]; wf[q] = pf[q]; }
    g_xg[t * FD + i] = 0.5f * dot32(wg, x2);
    g_xp[t * FD + i] = 0.5f * dot32(wp, x2);
    g_xd[t * FD + i] = dot32(wf, x2);
}

// ---------------- block-0 shared state ----------------
struct ScanSmem {
    float hfin[2][FD];   // final h_fast per step parity (warp0 writes)
    float wk0[FD];       // warp0 private relax buffers
    float wk1[FD];
    float shs[FD];       // h_slow in [0..15]; [16..31] = junk pad (warp1)
    float sdr[FD];       // sdrive vector (warp1 writes)
};

// ============================================================
// warp0: gate + relax (fast-state critical path only)
//   waits only on B (h_slow/sdrive ready); arrives only on A.
// ============================================================
__device__ void scan_warp0(int i, ScanSmem* S,
    const float* __restrict__ Wgh, const float* __restrict__ bgh_p,
    const float* __restrict__ Wff, const float* __restrict__ bff_p)
{
    ull wghH2[16], wff2[16];
#pragma unroll
    for (int q = 0; q < 16; q++)
        wghH2[q] = pack2(0.5f * Wgh[i * FD + 2 * q], 0.5f * Wgh[i * FD + 2 * q + 1]);
    {
        const ull* p1 = (const ull*)(Wff + (size_t)i * FD);
#pragma unroll
        for (int q = 0; q < 16; q++) wff2[q] = p1[q];
    }
    float bghH = 0.5f * bgh_p[i];
    float bff  = bff_p[i];

    S->hfin[0][i] = 0.f; S->hfin[1][i] = 0.f;
    float hf = 0.f;
    WFENCE();
    ARRIVE_A();                      // prime: h_fast(-1)=0 published

    // prefetch drives, biases folded in (off critical path)
    float cg[4], cp[4], cd[4];
#pragma unroll
    for (int k = 0; k < 4; k++) {
        cg[k] = g_xg[k * FD + i] + bghH;
        cp[k] = g_xp[k * FD + i];
        cd[k] = g_xd[k * FD + i] + bff;
    }

    for (int tg = 0; tg < T_STEPS / 4; tg++) {
        float ng[4], np[4], nd[4];
        if (tg + 1 < T_STEPS / 4) {
            int tb = (4 * tg + 4) * FD + i;
#pragma unroll
            for (int k = 0; k < 4; k++) {
                ng[k] = g_xg[tb + k * FD] + bghH;
                np[k] = g_xp[tb + k * FD];
                nd[k] = g_xd[tb + k * FD] + bff;
            }
        } else {
#pragma unroll
            for (int k = 0; k < 4; k++) { ng[k] = 0.f; np[k] = 0.f; nd[k] = 0.f; }
        }

#pragma unroll
        for (int k = 0; k < 4; k++) {
            int t = 4 * tg + k;
            const ulonglong2* hp2 = (const ulonglong2*)S->hfin[(t + 1) & 1];

            // gate stage — operands warp0-local (hfin written by warp0 last step)
            float gd = dot32i(wghH2, hp2, pack2(cg[k], 0.f));
            float tv = tanh_f(gd);
            float base = hf + cp[k];
            hf = fmaf(cp[k], tv, base);
            S->wk0[i] = hf;
            WFENCE();
            // relax1 dot — issued before the wait, completes during it
            float r1 = dot32i(wff2, (const ulonglong2*)S->wk0, pack2(cd[k], 0.f));
            float hf75 = 0.75f * hf;

            SYNC_B();                                  // h_slow(t-1)/sdrive ready

            float sdr = S->sdr[i];                     // scalar LDS
            float t1 = tanh_f(r1 + sdr);
            hf = fmaf(0.25f, t1, hf75);
            S->wk1[i] = hf;
            float hf75b = 0.75f * hf;
            WFENCE();
            float r2 = dot32i(wff2, (const ulonglong2*)S->wk1, pack2(cd[k], 0.f));
            float t2 = tanh_f(r2 + sdr);
            hf = fmaf(0.25f, t2, hf75b);
            S->hfin[t & 1][i] = hf;
            WFENCE();
            ARRIVE_A();                                // h_fast(t) published
        }
#pragma unroll
        for (int k = 0; k < 4; k++) { cg[k] = ng[k]; cp[k] = np[k]; cd[k] = nd[k]; }
    }
}

// ============================================================
// warp1: slow-state update + sdrive matvec + g_h copies + publish
//   waits only on A; arrives only on B.
// ============================================================
__device__ void scan_warp1(int i, ScanSmem* S,
    const float* __restrict__ Wsgf, const float* __restrict__ bsgf,
    const float* __restrict__ Wsgs,
    const float* __restrict__ Wss, const float* __restrict__ bss,
    const float* __restrict__ Wsf, const float* __restrict__ Wfs)
{
    ull ws2[24], wfs2[8];
    float bs;
    if (i < SD) {
        const ull* pa = (const ull*)(Wsgf + (size_t)i * FD);
        const ull* pb = (const ull*)(Wsgs + (size_t)i * SD);
#pragma unroll
        for (int q = 0; q < 16; q++) ws2[q] = pa[q];
#pragma unroll
        for (int q = 0; q < 8; q++) ws2[16 + q] = pb[q];
        bs = bsgf[i];
    } else {
        const ull* pa = (const ull*)(Wsf + (size_t)(i - SD) * FD);
        const ull* pb = (const ull*)(Wss + (size_t)(i - SD) * SD);
#pragma unroll
        for (int q = 0; q < 16; q++) ws2[q] = pa[q];
#pragma unroll
        for (int q = 0; q < 8; q++) ws2[16 + q] = pb[q];
        bs = bss[i - SD];
    }
    {
        const ull* p2 = (const ull*)(Wfs + (size_t)i * SD);
#pragma unroll
        for (int q = 0; q < 8; q++) wfs2[q] = p2[q];
    }
    S->shs[i] = 0.f;
    S->sdr[i] = 0.f;          // sdrive for t=0 (h_slow(-1)=0)
    float hs = 0.f;
    WFENCE();

    const ulonglong2* shs2 = (const ulonglong2*)S->shs;

    for (int t = 0; t < T_STEPS; t++) {
        // h_slow(t-2) half of the slow matvec — warp1-local, pre-wait
        float ssb = dot16i(ws2 + 16, shs2, pack2(bs, 0.f));

        SYNC_A();                                      // h_fast(t-1) ready

        if (t > 0) {
            const float* hp = S->hfin[(t + 1) & 1];
            float sacc = dot32i(ws2, (const ulonglong2*)hp, pack2(ssb, 0.f));
            float val = (i < SD) ? sig_f(sacc) : tanh_f(sacc);
            float prt = __shfl_xor_sync(0xffffffffu, val, 16);
            // all lanes compute (junk in lanes>=16), no divergence pre-sdrive
            hs = fmaf(0.02f * val, prt - hs, hs);
            S->shs[i] = hs;
            WFENCE();
            // sdrive = W_fs @ h_slow(t-1), all 32 output lanes
            float sd = dot16i(wfs2, shs2, pack2(0.f, 0.f));
            S->sdr[i] = sd;
            WFENCE();
            ARRIVE_B();
            // off-path: emit state row t-1
            float hfl = hp[i];
            g_h[(t - 1) * HD + i] = hfl;
            if (i < SD) g_h[(t - 1) * HD + FD + i] = hs;
            if (((t & 31) == 0) && i == 0) publish(t);
        } else {
            ARRIVE_B();
        }
    }

    // tail: slow update + row T-1
    {
        float ssb = dot16i(ws2 + 16, shs2, pack2(bs, 0.f));
        SYNC_A();
        const float* hp = S->hfin[(T_STEPS - 1) & 1];
        float sacc = dot32i(ws2, (const ulonglong2*)hp, pack2(ssb, 0.f));
        float val = (i < SD) ? sig_f(sacc) : tanh_f(sacc);
        float prt = __shfl_xor_sync(0xffffffffu, val, 16);
        hs = fmaf(0.02f * val, prt - hs, hs);
        float hfl = hp[i];
        g_h[(T_STEPS - 1) * HD + i] = hfl;
        if (i < SD) g_h[(T_STEPS - 1) * HD + FD + i] = hs;
        __syncwarp();
        if (i == 0) publish(T_STEPS);
    }
}

// ============================================================
// head tile — one (vb, tb) partial-sumexp tile (256 threads)
// ============================================================
__device__ void head_tile(int vb, int tb,
                          const float* __restrict__ Wout,
                          const float* __restrict__ bout)
{
    int tid = threadIdx.x;
    __shared__ __align__(16) float hsh[TT][HD];
    const float* hsrc = g_h + (size_t)tb * TT * HD;
    for (int k = tid; k < TT * HD; k += 256)
        ((float*)hsh)[k] = hsrc[k];
    __syncthreads();

    float acc[TT];
#pragma unroll
    for (int q = 0; q < TT; q++) acc[q] = 0.f;

    for (int vi = 0; vi < VBLOCK / 256; vi++) {
        int v = vb * VBLOCK + vi * 256 + tid;
        if (v < VOCAB) {
            ull w2[24];
            const ulonglong2* wp = (const ulonglong2*)(Wout + (size_t)v * HD);
#pragma unroll
            for (int q = 0; q < 12; q++) {
                ulonglong2 t4 = wp[q]; w2[2 * q] = t4.x; w2[2 * q + 1] = t4.y;
            }
            ull bo2 = pack2(bout[v], 0.f);
#pragma unroll 2
            for (int tt = 0; tt < TT; tt++) {
                const ulonglong2* hp = (const ulonglong2*)hsh[tt];
                ull a0 = bo2, a1 = 0, a2 = 0, a3 = 0;
#pragma unroll
                for (int m = 0; m < 12; m++) {
                    ulonglong2 pp = hp[m];
                    if (m & 1) { FMA2(a2, w2[2 * m], pp.x); FMA2(a3, w2[2 * m + 1], pp.y); }
                    else       { FMA2(a0, w2[2 * m], pp.x); FMA2(a1, w2[2 * m + 1], pp.y); }
                }
                acc[tt] += __expf(redu4(a0, a1, a2, a3));
            }
        }
    }

    __shared__ float swarp[8][TT];
    int lane = tid & 31, wrp = tid >> 5;
#pragma unroll
    for (int tt = 0; tt < TT; tt++) {
        float v = acc[tt];
        v += __shfl_xor_sync(0xffffffff, v, 16);
        v += __shfl_xor_sync(0xffffffff, v, 8);
        v += __shfl_xor_sync(0xffffffff, v, 4);
        v += __shfl_xor_sync(0xffffffff, v, 2);
        v += __shfl_xor_sync(0xffffffff, v, 1);
        if (lane == 0) swarp[wrp][tt] = v;
    }
    __syncthreads();
    if (tid < TT) {
        float s = 0.f;
#pragma unroll
        for (int q = 0; q < 8; q++) s += swarp[q][tid];
        g_partial[(size_t)vb * T_STEPS + tb * TT + tid] = s;
    }
    __syncthreads();
}

// ============================================================
// finale — NLL + mean
// ============================================================
__device__ void finale(const int* __restrict__ tok,
                       const float* __restrict__ Wout,
                       const float* __restrict__ bout,
                       float* __restrict__ out)
{
    int tid = threadIdx.x;
    float local = 0.f;
    for (int t = tid; t < T_STEPS; t += 256) {
        float s = 0.f;
#pragma unroll
        for (int vb = 0; vb < NVB; vb++) s += g_partial[(size_t)vb * T_STEPS + t];
        int tgt = tok[t + 1];
        const float* wr = Wout + (size_t)tgt * HD;
        const float* hr = g_h + t * HD;
        float a = bout[tgt];
#pragma unroll
        for (int k = 0; k < HD; k++) a = fmaf(wr[k], hr[k], a);
        local += logf(s) - a;
    }
    __shared__ float red[256];
    red[tid] = local;
    __syncthreads();
    for (int st = 128; st > 0; st >>= 1) {
        if (tid < st) red[tid] += red[tid + st];
        __syncthreads();
    }
    if (tid == 0) out[0] = red[0] / (float)T_STEPS;
}

// ============================================================
// fused persistent kernel
// ============================================================
__global__ void __launch_bounds__(256, 1) fused_kernel(
    const int* __restrict__ tok,
    const float* __restrict__ Wgh, const float* __restrict__ bgh,
    const float* __restrict__ Wff, const float* __restrict__ bff,
    const float* __restrict__ Wfs,
    const float* __restrict__ Wsgf, const float* __restrict__ bsgf,
    const float* __restrict__ Wsgs,
    const float* __restrict__ Wss, const float* __restrict__ bss,
    const float* __restrict__ Wsf,
    const float* __restrict__ Wout, const float* __restrict__ bout,
    float* __restrict__ out)
{
    int tid = threadIdx.x;

    if (blockIdx.x == 0) {
        __shared__ __align__(16) ScanSmem S;
        int lane = tid & 31;
        if (tid < 32)
            scan_warp0(lane, &S, Wgh, bgh, Wff, bff);
        else if (tid < 64)
            scan_warp1(lane, &S, Wsgf, bsgf, Wsgs, Wss, bss, Wsf, Wfs);
        return;
    }

    __shared__ int s_tile;
    __shared__ int s_flag;
    for (;;) {
        if (tid == 0) s_tile = atomicAdd(&g_tile, 1);
        __syncthreads();
        int tile = s_tile;
        if (tile >= TILES) break;
        int tb = tile / NVB;
        int vb = tile - tb * NVB;

        if (tid == 0) {
            int need = (tb + 1) * TT;
            while (load_prog() < need) __nanosleep(64);
        }
        __syncthreads();

        head_tile(vb, tb, Wout, bout);

        if (tid == 0) {
            __threadfence();
            int d = atomicAdd(&g_done, 1);
            s_flag = (d == TILES - 1);
        }
        __syncthreads();
        if (s_flag) {
            __threadfence();
            finale(tok, Wout, bout, out);
        }
        __syncthreads();
    }
}

// ============================================================
extern "C" void kernel_launch(void* const* d_in, const int* in_sizes, int n_in,
                              void* d_out, int out_size)
{
    const int*   tok   = (const int*)  d_in[0];
    const float* embed = (const float*)d_in[1];
    const float* Wgh   = (const float*)d_in[2];
    const float* bgh   = (const float*)d_in[3];
    const float* Wgx   = (const float*)d_in[4];
    const float* Wxp   = (const float*)d_in[5];
    const float* Wff   = (const float*)d_in[6];
    const float* bff   = (const float*)d_in[7];
    const float* Wfs   = (const float*)d_in[8];
    const float* Wxf   = (const float*)d_in[9];
    const float* Wsgf  = (const float*)d_in[10];
    const float* bsgf  = (const float*)d_in[11];
    const float* Wsgs  = (const float*)d_in[12];
    const float* Wss   = (const float*)d_in[13];
    const float* bss   = (const float*)d_in[14];
    const float* Wsf   = (const float*)d_in[15];
    const float* Wout  = (const float*)d_in[16];
    const float* bout  = (const float*)d_in[17];

    precompute_kernel<<<T_STEPS, 32>>>(tok, embed, Wgx, Wxp, Wxf);
    fused_kernel<<<NBLK, 256>>>(tok, Wgh, bgh, Wff, bff, Wfs,
                                Wsgf, bsgf, Wsgs, Wss, bss, Wsf,
                                Wout, bout, (float*)d_out);
}